// round 10
// baseline (speedup 1.0000x reference)
#include <cuda_runtime.h>
#include <cuda_fp16.h>
#include <math.h>

#define D 128
#define NMAX 50000
#define EMAX 800000
#define BM 64

// Scratch (device globals — zero-init at load; invariants: g_cnt zeroed by
// k_scan after use; g_degex zeroed at the start of each run by k_precnt).
__device__ uint2 g_xwh[(size_t)NMAX * 32];  // x @ W packed 4x fp16 per lane
__device__ float g_p1[NMAX];                // x . w_pred[:128]
__device__ float g_p2[NMAX];                // x . w_pred[128:]
__device__ float g_degex[NMAX];             // weighted in-degree EXCESS (deg-1)
__device__ int   g_cnt[NMAX];               // in-degree count (by tgt)
__device__ int   g_rowstart[NMAX + 1];      // CSR row offsets (by tgt)
__device__ int   g_cursor[NMAX];            // fill cursors
__device__ int2  g_pack[EMAX];              // (src, ew bits) grouped by tgt

// ---------------------------------------------------------------------------
// K1 (fused): blocks [0, npre): per-node dots with w_pred halves; also zeroes
//             g_degex for this run. blocks [npre, ...): in-degree counts by
//             target (g_cnt is zero: static init or zeroed by previous scan).
// ---------------------------------------------------------------------------
__global__ void k_precnt(const float* __restrict__ x,
                         const float* __restrict__ wp,
                         const int* __restrict__ tgt, int n, int e, int npre) {
    if ((int)blockIdx.x < npre) {
        int warp = (blockIdx.x * 256 + threadIdx.x) >> 5;
        int lane = threadIdx.x & 31;
        if (warp >= n) return;
        float4 xv = ((const float4*)(x + (size_t)warp * D))[lane];
        float4 w1 = ((const float4*)wp)[lane];
        float4 w2 = ((const float4*)(wp + D))[lane];
        float s1 = xv.x * w1.x + xv.y * w1.y + xv.z * w1.z + xv.w * w1.w;
        float s2 = xv.x * w2.x + xv.y * w2.y + xv.z * w2.z + xv.w * w2.w;
#pragma unroll
        for (int o = 16; o > 0; o >>= 1) {
            s1 += __shfl_xor_sync(0xffffffffu, s1, o);
            s2 += __shfl_xor_sync(0xffffffffu, s2, o);
        }
        if (lane == 0) {
            g_p1[warp] = s1;
            g_p2[warp] = s2;
            g_degex[warp] = 0.0f;  // reset for this run (read only downstream)
        }
    } else {
        int i = (blockIdx.x - npre) * 256 + threadIdx.x;
        if (i >= e) return;
        atomicAdd(&g_cnt[tgt[i]], 1);
    }
}

// ---------------------------------------------------------------------------
// K2: single-block 1024-thread exclusive scan of g_cnt (next-tile prefetch,
// coalesced) -> rowstart, cursor. Zeroes g_cnt after consuming it.
// ---------------------------------------------------------------------------
__global__ void k_scan(int n, int e) {
    __shared__ int wsum[32];
    int tid = threadIdx.x;
    int lane = tid & 31, wid = tid >> 5;
    int carry = 0;
    int v = (tid < n) ? g_cnt[tid] : 0;  // tile 0 prefetch

    for (int base = 0; base < n; base += 1024) {
        int i = base + tid;
        int inext = i + 1024;
        int vnext = (inext < n) ? g_cnt[inext] : 0;  // prefetch next tile
        if (i < n) g_cnt[i] = 0;                     // reset for next run

        int xinc = v;
#pragma unroll
        for (int o = 1; o < 32; o <<= 1) {
            int y = __shfl_up_sync(0xffffffffu, xinc, o);
            if (lane >= o) xinc += y;
        }
        if (lane == 31) wsum[wid] = xinc;
        __syncthreads();
        if (wid == 0) {
            int w = wsum[lane];
#pragma unroll
            for (int o = 1; o < 32; o <<= 1) {
                int y = __shfl_up_sync(0xffffffffu, w, o);
                if (lane >= o) w += y;
            }
            wsum[lane] = w;
        }
        __syncthreads();
        int woff = (wid > 0) ? wsum[wid - 1] : 0;
        int excl = carry + woff + xinc - v;
        if (i < n) {
            g_rowstart[i] = excl;
            g_cursor[i] = excl;
        }
        carry += wsum[31];
        __syncthreads();  // wsum reused next tile
        v = vnext;
    }
    if (tid == 0) g_rowstart[n] = e;
}

// ---------------------------------------------------------------------------
// K3 (fused): blocks [0, ngemm): FFMA2 GEMM -> fp16 xwh only.
//             blocks [ngemm, ...): edge sigmoid + degex atomics + CSR fill.
// Independent work, disjoint outputs (proven R8 overlap).
// ---------------------------------------------------------------------------
__global__ void k_gemmedge(const float* __restrict__ x,
                           const float* __restrict__ W,
                           const int* __restrict__ src,
                           const int* __restrict__ tgt,
                           const float* __restrict__ bp,
                           int n, int e, int ngemm) {
    if ((int)blockIdx.x >= ngemm) {
        int i = (blockIdx.x - ngemm) * 256 + threadIdx.x;
        if (i >= e) return;
        int s = src[i], t = tgt[i];
        float z = g_p1[s] + g_p2[t] + bp[0];
        float w = __fdividef(1.0f, 1.0f + __expf(-z));
        atomicAdd(&g_degex[t], w);
        int pos = atomicAdd(&g_cursor[t], 1);
        g_pack[pos] = make_int2(s, __float_as_int(w));
        return;
    }

    extern __shared__ float sh[];
    float* Ws = sh;            // [k][j]  128*128
    float* Xs = sh + D * D;    // [r][k]  BM*128
    int tid = threadIdx.x;
    int row0 = blockIdx.x * BM;

    for (int i = tid; i < D * D / 4; i += 256)
        ((float4*)Ws)[i] = ((const float4*)W)[i];
    for (int i = tid; i < BM * D / 4; i += 256) {
        int r = i >> 5;
        int gr = row0 + r;
        float4 v = make_float4(0.f, 0.f, 0.f, 0.f);
        if (gr < n) v = ((const float4*)x)[(size_t)gr * 32 + (i & 31)];
        ((float4*)Xs)[i] = v;
    }
    __syncthreads();

    int tcol = tid & 31;
    int trow = tid >> 5;

    unsigned long long acc[8][2];
#pragma unroll
    for (int i = 0; i < 8; i++) {
        acc[i][0] = 0ull;
        acc[i][1] = 0ull;
    }

#pragma unroll 4
    for (int k = 0; k < D; k++) {
        float4 bv = *((const float4*)&Ws[k * D + tcol * 4]);
        unsigned long long b01, b23;
        asm("mov.b64 %0, {%1, %2};" : "=l"(b01) : "f"(bv.x), "f"(bv.y));
        asm("mov.b64 %0, {%1, %2};" : "=l"(b23) : "f"(bv.z), "f"(bv.w));
#pragma unroll
        for (int i = 0; i < 8; i++) {
            float a = Xs[(trow * 8 + i) * D + k];
            unsigned long long aa;
            asm("mov.b64 %0, {%1, %1};" : "=l"(aa) : "f"(a));
            asm("fma.rn.f32x2 %0, %1, %2, %0;" : "+l"(acc[i][0])
                : "l"(aa), "l"(b01));
            asm("fma.rn.f32x2 %0, %1, %2, %0;" : "+l"(acc[i][1])
                : "l"(aa), "l"(b23));
        }
    }

#pragma unroll
    for (int i = 0; i < 8; i++) {
        int gr = row0 + trow * 8 + i;
        if (gr < n) {
            float c0, c1, c2, c3;
            asm("mov.b64 {%0, %1}, %2;" : "=f"(c0), "=f"(c1) : "l"(acc[i][0]));
            asm("mov.b64 {%0, %1}, %2;" : "=f"(c2), "=f"(c3) : "l"(acc[i][1]));
            __half2 h01 = __floats2half2_rn(c0, c1);
            __half2 h23 = __floats2half2_rn(c2, c3);
            uint2 pk;
            pk.x = *(unsigned*)&h01;
            pk.y = *(unsigned*)&h23;
            g_xwh[(size_t)gr * 32 + tcol] = pk;
        }
    }
}

// ---------------------------------------------------------------------------
// K4: atomic-free aggregation, warp per TARGET node. Lane-parallel edge
// metadata; 4-way unrolled fp16 row gathers. __launch_bounds__(256, 6) caps
// regs (~42) so 48 warps/SM fit — latency-bound kernel, occupancy lever.
// ---------------------------------------------------------------------------
__global__ void __launch_bounds__(256, 6)
k_aggregate(const float* __restrict__ b, float* __restrict__ out, int n) {
    int t = (blockIdx.x * blockDim.x + threadIdx.x) >> 5;
    int lane = threadIdx.x & 31;
    if (t >= n) return;
    float dt = rsqrtf(1.0f + g_degex[t]);
    uint2 sv = g_xwh[(size_t)t * 32 + lane];
    float2 sa = __half22float2(*(__half2*)&sv.x);
    float2 sb = __half22float2(*(__half2*)&sv.y);
    float sc = dt * dt;
    float4 acc = make_float4(sc * sa.x, sc * sa.y, sc * sb.x, sc * sb.y);

    int p0 = g_rowstart[t];
    int cnt = g_rowstart[t + 1] - p0;

    for (int base = 0; base < cnt; base += 32) {
        int idx = base + lane;
        int s = 0;
        float c = 0.f;
        if (idx < cnt) {
            int2 pk = g_pack[p0 + idx];
            s = pk.x;
            c = __int_as_float(pk.y) * rsqrtf(1.0f + g_degex[s]) * dt;
        }
        int m = min(32, cnt - base);
        int j = 0;
        for (; j + 4 <= m; j += 4) {
            int s0 = __shfl_sync(0xffffffffu, s, j);
            int s1 = __shfl_sync(0xffffffffu, s, j + 1);
            int s2 = __shfl_sync(0xffffffffu, s, j + 2);
            int s3 = __shfl_sync(0xffffffffu, s, j + 3);
            float c0 = __shfl_sync(0xffffffffu, c, j);
            float c1 = __shfl_sync(0xffffffffu, c, j + 1);
            float c2 = __shfl_sync(0xffffffffu, c, j + 2);
            float c3 = __shfl_sync(0xffffffffu, c, j + 3);
            uint2 v0 = g_xwh[(size_t)s0 * 32 + lane];
            uint2 v1 = g_xwh[(size_t)s1 * 32 + lane];
            uint2 v2 = g_xwh[(size_t)s2 * 32 + lane];
            uint2 v3 = g_xwh[(size_t)s3 * 32 + lane];
            float2 a0 = __half22float2(*(__half2*)&v0.x);
            float2 d0 = __half22float2(*(__half2*)&v0.y);
            float2 a1 = __half22float2(*(__half2*)&v1.x);
            float2 d1 = __half22float2(*(__half2*)&v1.y);
            float2 a2 = __half22float2(*(__half2*)&v2.x);
            float2 d2 = __half22float2(*(__half2*)&v2.y);
            float2 a3 = __half22float2(*(__half2*)&v3.x);
            float2 d3 = __half22float2(*(__half2*)&v3.y);
            acc.x += c0 * a0.x + c1 * a1.x + c2 * a2.x + c3 * a3.x;
            acc.y += c0 * a0.y + c1 * a1.y + c2 * a2.y + c3 * a3.y;
            acc.z += c0 * d0.x + c1 * d1.x + c2 * d2.x + c3 * d3.x;
            acc.w += c0 * d0.y + c1 * d1.y + c2 * d2.y + c3 * d3.y;
        }
        for (; j < m; j++) {
            int sj = __shfl_sync(0xffffffffu, s, j);
            float cj = __shfl_sync(0xffffffffu, c, j);
            uint2 v = g_xwh[(size_t)sj * 32 + lane];
            float2 a = __half22float2(*(__half2*)&v.x);
            float2 d = __half22float2(*(__half2*)&v.y);
            acc.x += cj * a.x;
            acc.y += cj * a.y;
            acc.z += cj * d.x;
            acc.w += cj * d.y;
        }
    }

    float4 bv = ((const float4*)b)[lane];
    ((float4*)out)[(size_t)t * 32 + lane] =
        make_float4(acc.x + bv.x, acc.y + bv.y, acc.z + bv.z, acc.w + bv.w);
}

// ---------------------------------------------------------------------------
extern "C" void kernel_launch(void* const* d_in, const int* in_sizes, int n_in,
                              void* d_out, int out_size) {
    const float* x  = (const float*)d_in[0];
    const int*   ei = (const int*)d_in[1];
    const float* W  = (const float*)d_in[2];
    const float* b  = (const float*)d_in[3];
    const float* wp = (const float*)d_in[4];
    const float* bp = (const float*)d_in[5];
    float* out = (float*)d_out;

    int n = in_sizes[0] / D;
    int e = in_sizes[1] / 2;
    const int* src = ei;
    const int* tgt = ei + e;
    int npre = (n + 7) / 8;         // precompute blocks (8 warps each)
    int neb = (e + 255) / 256;      // cnt / edgefill blocks
    int ngemm = (n + BM - 1) / BM;  // gemm blocks

    int smem = (D * D + BM * D) * (int)sizeof(float);  // 96 KB
    cudaFuncSetAttribute(k_gemmedge, cudaFuncAttributeMaxDynamicSharedMemorySize,
                         smem);

    k_precnt<<<npre + neb, 256>>>(x, wp, tgt, n, e, npre);
    k_scan<<<1, 1024>>>(n, e);
    k_gemmedge<<<ngemm + neb, 256, smem>>>(x, W, src, tgt, bp, n, e, ngemm);
    k_aggregate<<<(n * 32 + 255) / 256, 256>>>(b, out, n);
}

// round 11
// speedup vs baseline: 1.1287x; 1.1287x over previous
#include <cuda_runtime.h>
#include <cuda_fp16.h>
#include <math.h>

#define D 128
#define NMAX 50000
#define EMAX 800000
#define BM 64

// Scratch (device globals — zero-initialized at load; k_reset keeps them zero)
__device__ float g_xw[(size_t)NMAX * D];    // x @ W (fp32, self term)
__device__ uint2 g_xwh[(size_t)NMAX * 32];  // x @ W packed 4x fp16 per lane
__device__ float g_p1[NMAX];                // x . w_pred[:128]
__device__ float g_p2[NMAX];                // x . w_pred[128:]
__device__ float g_degex[NMAX];             // weighted in-degree EXCESS (deg-1)
__device__ int   g_cnt[NMAX];               // in-degree count (by tgt)
__device__ int   g_rowstart[NMAX + 1];      // CSR row offsets (by tgt)
__device__ int   g_cursor[NMAX];            // fill cursors
__device__ int2  g_pack[EMAX];              // (src, ew bits) grouped by tgt
__device__ int   g_bsum[256];               // block sums for scan
__device__ int   g_boff[256];               // block offsets for scan

// ---------------------------------------------------------------------------
// K1 (fused): blocks [0, npre): per-node dots with w_pred halves.
//             blocks [npre, ...): in-degree counts by target (g_cnt starts 0).
// ---------------------------------------------------------------------------
__global__ void k_precnt(const float* __restrict__ x,
                         const float* __restrict__ wp,
                         const int* __restrict__ tgt, int n, int e, int npre) {
    if ((int)blockIdx.x < npre) {
        int warp = (blockIdx.x * 256 + threadIdx.x) >> 5;
        int lane = threadIdx.x & 31;
        if (warp >= n) return;
        float4 xv = ((const float4*)(x + (size_t)warp * D))[lane];
        float4 w1 = ((const float4*)wp)[lane];
        float4 w2 = ((const float4*)(wp + D))[lane];
        float s1 = xv.x * w1.x + xv.y * w1.y + xv.z * w1.z + xv.w * w1.w;
        float s2 = xv.x * w2.x + xv.y * w2.y + xv.z * w2.z + xv.w * w2.w;
#pragma unroll
        for (int o = 16; o > 0; o >>= 1) {
            s1 += __shfl_xor_sync(0xffffffffu, s1, o);
            s2 += __shfl_xor_sync(0xffffffffu, s2, o);
        }
        if (lane == 0) {
            g_p1[warp] = s1;
            g_p2[warp] = s2;
        }
    } else {
        int i = (blockIdx.x - npre) * 256 + threadIdx.x;
        if (i >= e) return;
        atomicAdd(&g_cnt[tgt[i]], 1);
    }
}

// ---------------------------------------------------------------------------
// K2a/b/c: coalesced 3-phase exclusive scan of g_cnt -> rowstart/cursor.
// ---------------------------------------------------------------------------
__global__ void k_scan1(int n) {
    __shared__ int sd[256];
    int tid = threadIdx.x;
    int i = blockIdx.x * 256 + tid;
    int v = (i < n) ? g_cnt[i] : 0;
    sd[tid] = v;
    __syncthreads();
#pragma unroll
    for (int off = 1; off < 256; off <<= 1) {
        int u = (tid >= off) ? sd[tid - off] : 0;
        __syncthreads();
        sd[tid] += u;
        __syncthreads();
    }
    if (i < n) g_rowstart[i] = sd[tid] - v;
    if (tid == 255) g_bsum[blockIdx.x] = sd[255];
}

__global__ void k_scan2(int nb) {
    __shared__ int sd[256];
    int tid = threadIdx.x;
    int v = (tid < nb) ? g_bsum[tid] : 0;
    sd[tid] = v;
    __syncthreads();
#pragma unroll
    for (int off = 1; off < 256; off <<= 1) {
        int u = (tid >= off) ? sd[tid - off] : 0;
        __syncthreads();
        sd[tid] += u;
        __syncthreads();
    }
    g_boff[tid] = sd[tid] - v;
}

__global__ void k_scan3(int n, int e) {
    int i = blockIdx.x * 256 + threadIdx.x;
    if (i < n) {
        int r = g_rowstart[i] + g_boff[blockIdx.x];
        g_rowstart[i] = r;
        g_cursor[i] = r;
    }
    if (i == 0) g_rowstart[n] = e;
}

// ---------------------------------------------------------------------------
// K3 (fused): blocks [0, ngemm): FFMA2 GEMM (writes fp32 g_xw + fp16 g_xwh).
//             blocks [ngemm, ...): edge sigmoid + degex atomics + CSR fill.
// ---------------------------------------------------------------------------
__global__ void k_gemmedge(const float* __restrict__ x,
                           const float* __restrict__ W,
                           const int* __restrict__ src,
                           const int* __restrict__ tgt,
                           const float* __restrict__ bp,
                           int n, int e, int ngemm) {
    if ((int)blockIdx.x >= ngemm) {
        int i = (blockIdx.x - ngemm) * 256 + threadIdx.x;
        if (i >= e) return;
        int s = src[i], t = tgt[i];
        float z = g_p1[s] + g_p2[t] + bp[0];
        float w = __fdividef(1.0f, 1.0f + __expf(-z));
        atomicAdd(&g_degex[t], w);
        int pos = atomicAdd(&g_cursor[t], 1);
        g_pack[pos] = make_int2(s, __float_as_int(w));
        return;
    }

    extern __shared__ float sh[];
    float* Ws = sh;            // [k][j]  128*128
    float* Xs = sh + D * D;    // [r][k]  BM*128
    int tid = threadIdx.x;
    int row0 = blockIdx.x * BM;

    for (int i = tid; i < D * D / 4; i += 256)
        ((float4*)Ws)[i] = ((const float4*)W)[i];
    for (int i = tid; i < BM * D / 4; i += 256) {
        int r = i >> 5;
        int gr = row0 + r;
        float4 v = make_float4(0.f, 0.f, 0.f, 0.f);
        if (gr < n) v = ((const float4*)x)[(size_t)gr * 32 + (i & 31)];
        ((float4*)Xs)[i] = v;
    }
    __syncthreads();

    int tcol = tid & 31;
    int trow = tid >> 5;

    unsigned long long acc[8][2];
#pragma unroll
    for (int i = 0; i < 8; i++) {
        acc[i][0] = 0ull;
        acc[i][1] = 0ull;
    }

#pragma unroll 4
    for (int k = 0; k < D; k++) {
        float4 bv = *((const float4*)&Ws[k * D + tcol * 4]);
        unsigned long long b01, b23;
        asm("mov.b64 %0, {%1, %2};" : "=l"(b01) : "f"(bv.x), "f"(bv.y));
        asm("mov.b64 %0, {%1, %2};" : "=l"(b23) : "f"(bv.z), "f"(bv.w));
#pragma unroll
        for (int i = 0; i < 8; i++) {
            float a = Xs[(trow * 8 + i) * D + k];
            unsigned long long aa;
            asm("mov.b64 %0, {%1, %1};" : "=l"(aa) : "f"(a));
            asm("fma.rn.f32x2 %0, %1, %2, %0;" : "+l"(acc[i][0])
                : "l"(aa), "l"(b01));
            asm("fma.rn.f32x2 %0, %1, %2, %0;" : "+l"(acc[i][1])
                : "l"(aa), "l"(b23));
        }
    }

#pragma unroll
    for (int i = 0; i < 8; i++) {
        int gr = row0 + trow * 8 + i;
        if (gr < n) {
            float c0, c1, c2, c3;
            asm("mov.b64 {%0, %1}, %2;" : "=f"(c0), "=f"(c1) : "l"(acc[i][0]));
            asm("mov.b64 {%0, %1}, %2;" : "=f"(c2), "=f"(c3) : "l"(acc[i][1]));
            *((float4*)&g_xw[(size_t)gr * D + tcol * 4]) =
                make_float4(c0, c1, c2, c3);
            __half2 h01 = __floats2half2_rn(c0, c1);
            __half2 h23 = __floats2half2_rn(c2, c3);
            uint2 pk;
            pk.x = *(unsigned*)&h01;
            pk.y = *(unsigned*)&h23;
            g_xwh[(size_t)gr * 32 + tcol] = pk;
        }
    }
}

// ---------------------------------------------------------------------------
// K4: atomic-free aggregation, warp per TARGET node (R8 body) with the R10-
// PROVEN occupancy fix: __launch_bounds__(256, 6) -> regs<=40, 48 warps/SM.
// ---------------------------------------------------------------------------
__global__ void __launch_bounds__(256, 6)
k_aggregate(const float* __restrict__ b, float* __restrict__ out, int n) {
    int t = (blockIdx.x * blockDim.x + threadIdx.x) >> 5;
    int lane = threadIdx.x & 31;
    if (t >= n) return;
    float dt = rsqrtf(1.0f + g_degex[t]);
    float4 xv = ((const float4*)g_xw)[(size_t)t * 32 + lane];
    float sc = dt * dt;
    float4 acc = make_float4(sc * xv.x, sc * xv.y, sc * xv.z, sc * xv.w);

    int p0 = g_rowstart[t];
    int cnt = g_rowstart[t + 1] - p0;

    for (int base = 0; base < cnt; base += 32) {
        int idx = base + lane;
        int s = 0;
        float c = 0.f;
        if (idx < cnt) {
            int2 pk = g_pack[p0 + idx];
            s = pk.x;
            c = __int_as_float(pk.y) * rsqrtf(1.0f + g_degex[s]) * dt;
        }
        int m = min(32, cnt - base);
        int j = 0;
        for (; j + 4 <= m; j += 4) {
            int s0 = __shfl_sync(0xffffffffu, s, j);
            int s1 = __shfl_sync(0xffffffffu, s, j + 1);
            int s2 = __shfl_sync(0xffffffffu, s, j + 2);
            int s3 = __shfl_sync(0xffffffffu, s, j + 3);
            float c0 = __shfl_sync(0xffffffffu, c, j);
            float c1 = __shfl_sync(0xffffffffu, c, j + 1);
            float c2 = __shfl_sync(0xffffffffu, c, j + 2);
            float c3 = __shfl_sync(0xffffffffu, c, j + 3);
            uint2 v0 = g_xwh[(size_t)s0 * 32 + lane];
            uint2 v1 = g_xwh[(size_t)s1 * 32 + lane];
            uint2 v2 = g_xwh[(size_t)s2 * 32 + lane];
            uint2 v3 = g_xwh[(size_t)s3 * 32 + lane];
            float2 a0 = __half22float2(*(__half2*)&v0.x);
            float2 d0 = __half22float2(*(__half2*)&v0.y);
            float2 a1 = __half22float2(*(__half2*)&v1.x);
            float2 d1 = __half22float2(*(__half2*)&v1.y);
            float2 a2 = __half22float2(*(__half2*)&v2.x);
            float2 d2 = __half22float2(*(__half2*)&v2.y);
            float2 a3 = __half22float2(*(__half2*)&v3.x);
            float2 d3 = __half22float2(*(__half2*)&v3.y);
            acc.x += c0 * a0.x + c1 * a1.x + c2 * a2.x + c3 * a3.x;
            acc.y += c0 * a0.y + c1 * a1.y + c2 * a2.y + c3 * a3.y;
            acc.z += c0 * d0.x + c1 * d1.x + c2 * d2.x + c3 * d3.x;
            acc.w += c0 * d0.y + c1 * d1.y + c2 * d2.y + c3 * d3.y;
        }
        for (; j < m; j++) {
            int sj = __shfl_sync(0xffffffffu, s, j);
            float cj = __shfl_sync(0xffffffffu, c, j);
            uint2 v = g_xwh[(size_t)sj * 32 + lane];
            float2 a = __half22float2(*(__half2*)&v.x);
            float2 d = __half22float2(*(__half2*)&v.y);
            acc.x += cj * a.x;
            acc.y += cj * a.y;
            acc.z += cj * d.x;
            acc.w += cj * d.y;
        }
    }

    float4 bv = ((const float4*)b)[lane];
    ((float4*)out)[(size_t)t * 32 + lane] =
        make_float4(acc.x + bv.x, acc.y + bv.y, acc.z + bv.z, acc.w + bv.w);
}

// ---------------------------------------------------------------------------
// K5: restore g_cnt/g_degex to zero so every invocation starts identically.
// ---------------------------------------------------------------------------
__global__ void k_reset(int n) {
    int i = blockIdx.x * blockDim.x + threadIdx.x;
    if (i >= n) return;
    g_cnt[i] = 0;
    g_degex[i] = 0.0f;
}

// ---------------------------------------------------------------------------
extern "C" void kernel_launch(void* const* d_in, const int* in_sizes, int n_in,
                              void* d_out, int out_size) {
    const float* x  = (const float*)d_in[0];
    const int*   ei = (const int*)d_in[1];
    const float* W  = (const float*)d_in[2];
    const float* b  = (const float*)d_in[3];
    const float* wp = (const float*)d_in[4];
    const float* bp = (const float*)d_in[5];
    float* out = (float*)d_out;

    int n = in_sizes[0] / D;
    int e = in_sizes[1] / 2;
    const int* src = ei;
    const int* tgt = ei + e;
    int nb = (n + 255) / 256;        // scan blocks (<=256)
    int npre = (n + 7) / 8;          // precompute blocks (8 warps each)
    int ncntb = (e + 255) / 256;     // cnt / edgefill blocks
    int ngemm = (n + BM - 1) / BM;   // gemm blocks

    int smem = (D * D + BM * D) * (int)sizeof(float);  // 96 KB
    cudaFuncSetAttribute(k_gemmedge, cudaFuncAttributeMaxDynamicSharedMemorySize,
                         smem);

    k_precnt<<<npre + ncntb, 256>>>(x, wp, tgt, n, e, npre);
    k_scan1<<<nb, 256>>>(n);
    k_scan2<<<1, 256>>>(nb);
    k_scan3<<<nb, 256>>>(n, e);
    k_gemmedge<<<ngemm + ncntb, 256, smem>>>(x, W, src, tgt, bp, n, e, ngemm);
    k_aggregate<<<(n * 32 + 255) / 256, 256>>>(b, out, n);
    k_reset<<<nb, 256>>>(n);
}

// round 12
// speedup vs baseline: 1.1495x; 1.0184x over previous
#include <cuda_runtime.h>
#include <cuda_fp16.h>
#include <math.h>

#define D 128
#define NMAX 50000
#define EMAX 800000
#define BM 64

// Scratch (device globals — zero-initialized at load; k_scan23 re-zeroes
// g_cnt/g_degex each run so every invocation starts identically).
__device__ float g_xw[(size_t)NMAX * D];    // x @ W (fp32, self term)
__device__ uint2 g_xwh[(size_t)NMAX * 32];  // x @ W packed 4x fp16 per lane
__device__ float g_p1[NMAX];                // x . w_pred[:128]
__device__ float g_p2[NMAX];                // x . w_pred[128:]
__device__ float g_degex[NMAX];             // weighted in-degree EXCESS (deg-1)
__device__ int   g_cnt[NMAX];               // in-degree count (by tgt)
__device__ int   g_rowstart[NMAX + 1];      // CSR row offsets (by tgt)
__device__ int   g_cursor[NMAX];            // fill cursors
__device__ int2  g_pack[EMAX];              // (src, ew bits) grouped by tgt
__device__ int   g_bsum[256];               // block sums for scan

// ---------------------------------------------------------------------------
// K1 (fused): blocks [0, npre): per-node dots with w_pred halves.
//             blocks [npre, ...): in-degree counts by target (g_cnt starts 0).
// ---------------------------------------------------------------------------
__global__ void k_precnt(const float* __restrict__ x,
                         const float* __restrict__ wp,
                         const int* __restrict__ tgt, int n, int e, int npre) {
    if ((int)blockIdx.x < npre) {
        int warp = (blockIdx.x * 256 + threadIdx.x) >> 5;
        int lane = threadIdx.x & 31;
        if (warp >= n) return;
        float4 xv = ((const float4*)(x + (size_t)warp * D))[lane];
        float4 w1 = ((const float4*)wp)[lane];
        float4 w2 = ((const float4*)(wp + D))[lane];
        float s1 = xv.x * w1.x + xv.y * w1.y + xv.z * w1.z + xv.w * w1.w;
        float s2 = xv.x * w2.x + xv.y * w2.y + xv.z * w2.z + xv.w * w2.w;
#pragma unroll
        for (int o = 16; o > 0; o >>= 1) {
            s1 += __shfl_xor_sync(0xffffffffu, s1, o);
            s2 += __shfl_xor_sync(0xffffffffu, s2, o);
        }
        if (lane == 0) {
            g_p1[warp] = s1;
            g_p2[warp] = s2;
        }
    } else {
        int i = (blockIdx.x - npre) * 256 + threadIdx.x;
        if (i >= e) return;
        atomicAdd(&g_cnt[tgt[i]], 1);
    }
}

// ---------------------------------------------------------------------------
// K2a: per-block exclusive scan of g_cnt; block sums -> g_bsum.
// ---------------------------------------------------------------------------
__global__ void k_scan1(int n) {
    __shared__ int sd[256];
    int tid = threadIdx.x;
    int i = blockIdx.x * 256 + tid;
    int v = (i < n) ? g_cnt[i] : 0;
    sd[tid] = v;
    __syncthreads();
#pragma unroll
    for (int off = 1; off < 256; off <<= 1) {
        int u = (tid >= off) ? sd[tid - off] : 0;
        __syncthreads();
        sd[tid] += u;
        __syncthreads();
    }
    if (i < n) g_rowstart[i] = sd[tid] - v;
    if (tid == 255) g_bsum[blockIdx.x] = sd[255];
}

// ---------------------------------------------------------------------------
// K2b (fused scan2+scan3+reset): every block redundantly scans the tiny
// g_bsum array in smem (nb<=256, ~1us), applies its own offset to finalize
// rowstart/cursor, and re-zeroes g_cnt/g_degex for the next invocation.
// ---------------------------------------------------------------------------
__global__ void k_scan23(int n, int e, int nb) {
    __shared__ int sd[256];
    int tid = threadIdx.x;
    int v = (tid < nb) ? g_bsum[tid] : 0;
    sd[tid] = v;
    __syncthreads();
#pragma unroll
    for (int off = 1; off < 256; off <<= 1) {
        int u = (tid >= off) ? sd[tid - off] : 0;
        __syncthreads();
        sd[tid] += u;
        __syncthreads();
    }
    int boff = (blockIdx.x > 0) ? sd[blockIdx.x - 1] : 0;  // exclusive
    int i = blockIdx.x * 256 + tid;
    if (i < n) {
        int r = g_rowstart[i] + boff;
        g_rowstart[i] = r;
        g_cursor[i] = r;
        g_cnt[i] = 0;       // reset for next run
        g_degex[i] = 0.0f;  // reset for next run (written only downstream)
    }
    if (i == 0) g_rowstart[n] = e;
}

// ---------------------------------------------------------------------------
// K3 (fused): blocks [0, ngemm): FFMA2 GEMM (writes fp32 g_xw + fp16 g_xwh).
//             blocks [ngemm, ...): edge sigmoid + degex atomics + CSR fill.
// ---------------------------------------------------------------------------
__global__ void k_gemmedge(const float* __restrict__ x,
                           const float* __restrict__ W,
                           const int* __restrict__ src,
                           const int* __restrict__ tgt,
                           const float* __restrict__ bp,
                           int n, int e, int ngemm) {
    if ((int)blockIdx.x >= ngemm) {
        int i = (blockIdx.x - ngemm) * 256 + threadIdx.x;
        if (i >= e) return;
        int s = src[i], t = tgt[i];
        float z = g_p1[s] + g_p2[t] + bp[0];
        float w = __fdividef(1.0f, 1.0f + __expf(-z));
        atomicAdd(&g_degex[t], w);
        int pos = atomicAdd(&g_cursor[t], 1);
        g_pack[pos] = make_int2(s, __float_as_int(w));
        return;
    }

    extern __shared__ float sh[];
    float* Ws = sh;            // [k][j]  128*128
    float* Xs = sh + D * D;    // [r][k]  BM*128
    int tid = threadIdx.x;
    int row0 = blockIdx.x * BM;

    for (int i = tid; i < D * D / 4; i += 256)
        ((float4*)Ws)[i] = ((const float4*)W)[i];
    for (int i = tid; i < BM * D / 4; i += 256) {
        int r = i >> 5;
        int gr = row0 + r;
        float4 v = make_float4(0.f, 0.f, 0.f, 0.f);
        if (gr < n) v = ((const float4*)x)[(size_t)gr * 32 + (i & 31)];
        ((float4*)Xs)[i] = v;
    }
    __syncthreads();

    int tcol = tid & 31;
    int trow = tid >> 5;

    unsigned long long acc[8][2];
#pragma unroll
    for (int i = 0; i < 8; i++) {
        acc[i][0] = 0ull;
        acc[i][1] = 0ull;
    }

#pragma unroll 4
    for (int k = 0; k < D; k++) {
        float4 bv = *((const float4*)&Ws[k * D + tcol * 4]);
        unsigned long long b01, b23;
        asm("mov.b64 %0, {%1, %2};" : "=l"(b01) : "f"(bv.x), "f"(bv.y));
        asm("mov.b64 %0, {%1, %2};" : "=l"(b23) : "f"(bv.z), "f"(bv.w));
#pragma unroll
        for (int i = 0; i < 8; i++) {
            float a = Xs[(trow * 8 + i) * D + k];
            unsigned long long aa;
            asm("mov.b64 %0, {%1, %1};" : "=l"(aa) : "f"(a));
            asm("fma.rn.f32x2 %0, %1, %2, %0;" : "+l"(acc[i][0])
                : "l"(aa), "l"(b01));
            asm("fma.rn.f32x2 %0, %1, %2, %0;" : "+l"(acc[i][1])
                : "l"(aa), "l"(b23));
        }
    }

#pragma unroll
    for (int i = 0; i < 8; i++) {
        int gr = row0 + trow * 8 + i;
        if (gr < n) {
            float c0, c1, c2, c3;
            asm("mov.b64 {%0, %1}, %2;" : "=f"(c0), "=f"(c1) : "l"(acc[i][0]));
            asm("mov.b64 {%0, %1}, %2;" : "=f"(c2), "=f"(c3) : "l"(acc[i][1]));
            *((float4*)&g_xw[(size_t)gr * D + tcol * 4]) =
                make_float4(c0, c1, c2, c3);
            __half2 h01 = __floats2half2_rn(c0, c1);
            __half2 h23 = __floats2half2_rn(c2, c3);
            uint2 pk;
            pk.x = *(unsigned*)&h01;
            pk.y = *(unsigned*)&h23;
            g_xwh[(size_t)gr * 32 + tcol] = pk;
        }
    }
}

// ---------------------------------------------------------------------------
// K4: atomic-free aggregation, warp per TARGET node; __launch_bounds__(256,6)
// (R10-proven: regs<=40, 48 warps/SM). 4-way unrolled fp16 row gathers.
// ---------------------------------------------------------------------------
__global__ void __launch_bounds__(256, 6)
k_aggregate(const float* __restrict__ b, float* __restrict__ out, int n) {
    int t = (blockIdx.x * blockDim.x + threadIdx.x) >> 5;
    int lane = threadIdx.x & 31;
    if (t >= n) return;
    float dt = rsqrtf(1.0f + g_degex[t]);
    float4 xv = ((const float4*)g_xw)[(size_t)t * 32 + lane];
    float sc = dt * dt;
    float4 acc = make_float4(sc * xv.x, sc * xv.y, sc * xv.z, sc * xv.w);

    int p0 = g_rowstart[t];
    int cnt = g_rowstart[t + 1] - p0;

    for (int base = 0; base < cnt; base += 32) {
        int idx = base + lane;
        int s = 0;
        float c = 0.f;
        if (idx < cnt) {
            int2 pk = g_pack[p0 + idx];
            s = pk.x;
            c = __int_as_float(pk.y) * rsqrtf(1.0f + g_degex[s]) * dt;
        }
        int m = min(32, cnt - base);
        int j = 0;
        for (; j + 4 <= m; j += 4) {
            int s0 = __shfl_sync(0xffffffffu, s, j);
            int s1 = __shfl_sync(0xffffffffu, s, j + 1);
            int s2 = __shfl_sync(0xffffffffu, s, j + 2);
            int s3 = __shfl_sync(0xffffffffu, s, j + 3);
            float c0 = __shfl_sync(0xffffffffu, c, j);
            float c1 = __shfl_sync(0xffffffffu, c, j + 1);
            float c2 = __shfl_sync(0xffffffffu, c, j + 2);
            float c3 = __shfl_sync(0xffffffffu, c, j + 3);
            uint2 v0 = g_xwh[(size_t)s0 * 32 + lane];
            uint2 v1 = g_xwh[(size_t)s1 * 32 + lane];
            uint2 v2 = g_xwh[(size_t)s2 * 32 + lane];
            uint2 v3 = g_xwh[(size_t)s3 * 32 + lane];
            float2 a0 = __half22float2(*(__half2*)&v0.x);
            float2 d0 = __half22float2(*(__half2*)&v0.y);
            float2 a1 = __half22float2(*(__half2*)&v1.x);
            float2 d1 = __half22float2(*(__half2*)&v1.y);
            float2 a2 = __half22float2(*(__half2*)&v2.x);
            float2 d2 = __half22float2(*(__half2*)&v2.y);
            float2 a3 = __half22float2(*(__half2*)&v3.x);
            float2 d3 = __half22float2(*(__half2*)&v3.y);
            acc.x += c0 * a0.x + c1 * a1.x + c2 * a2.x + c3 * a3.x;
            acc.y += c0 * a0.y + c1 * a1.y + c2 * a2.y + c3 * a3.y;
            acc.z += c0 * d0.x + c1 * d1.x + c2 * d2.x + c3 * d3.x;
            acc.w += c0 * d0.y + c1 * d1.y + c2 * d2.y + c3 * d3.y;
        }
        for (; j < m; j++) {
            int sj = __shfl_sync(0xffffffffu, s, j);
            float cj = __shfl_sync(0xffffffffu, c, j);
            uint2 v = g_xwh[(size_t)sj * 32 + lane];
            float2 a = __half22float2(*(__half2*)&v.x);
            float2 d = __half22float2(*(__half2*)&v.y);
            acc.x += cj * a.x;
            acc.y += cj * a.y;
            acc.z += cj * d.x;
            acc.w += cj * d.y;
        }
    }

    float4 bv = ((const float4*)b)[lane];
    ((float4*)out)[(size_t)t * 32 + lane] =
        make_float4(acc.x + bv.x, acc.y + bv.y, acc.z + bv.z, acc.w + bv.w);
}

// ---------------------------------------------------------------------------
extern "C" void kernel_launch(void* const* d_in, const int* in_sizes, int n_in,
                              void* d_out, int out_size) {
    const float* x  = (const float*)d_in[0];
    const int*   ei = (const int*)d_in[1];
    const float* W  = (const float*)d_in[2];
    const float* b  = (const float*)d_in[3];
    const float* wp = (const float*)d_in[4];
    const float* bp = (const float*)d_in[5];
    float* out = (float*)d_out;

    int n = in_sizes[0] / D;
    int e = in_sizes[1] / 2;
    const int* src = ei;
    const int* tgt = ei + e;
    int nb = (n + 255) / 256;        // scan blocks (<=256)
    int npre = (n + 7) / 8;          // precompute blocks (8 warps each)
    int ncntb = (e + 255) / 256;     // cnt / edgefill blocks
    int ngemm = (n + BM - 1) / BM;   // gemm blocks

    int smem = (D * D + BM * D) * (int)sizeof(float);  // 96 KB
    cudaFuncSetAttribute(k_gemmedge, cudaFuncAttributeMaxDynamicSharedMemorySize,
                         smem);

    k_precnt<<<npre + ncntb, 256>>>(x, wp, tgt, n, e, npre);
    k_scan1<<<nb, 256>>>(n);
    k_scan23<<<nb, 256>>>(n, e, nb);
    k_gemmedge<<<ngemm + ncntb, 256, smem>>>(x, W, src, tgt, bp, n, e, ngemm);
    k_aggregate<<<(n * 32 + 255) / 256, 256>>>(b, out, n);
}